// round 1
// baseline (speedup 1.0000x reference)
#include <cuda_runtime.h>
#include <math.h>

#define NN 40000
#define NE 640000
#define ET 680000       // NE + NN self loops
#define C  128
#define NG 64
#define OC 16
#define EPS 1e-16f

// ---------------- scratch (device globals; no allocation allowed) ----------------
__device__ float    g_h  [(size_t)NN * C];
__device__ float    g_t1 [(size_t)NN * C];
__device__ float    g_t2 [(size_t)NN * C];
__device__ float    g_s  [NN];
__device__ unsigned g_m  [NN];
__device__ float    g_z  [NN];
__device__ float    g_alpha[ET];
__device__ float    g_dinv[NN];
__device__ int      g_hist[NN];
__device__ int      g_rp  [NN + 1];
__device__ int      g_cur [NN];
__device__ int      g_csrc[ET];
__device__ int      g_ceid[ET];
__device__ int      g_bsum[64];
__device__ float    g_pool[NG * C];
__device__ float    g_cnt [NG];

// ordered-uint encoding for float atomicMax
__device__ __forceinline__ unsigned fenc(float f) {
    unsigned u = __float_as_uint(f);
    return (u & 0x80000000u) ? ~u : (u | 0x80000000u);
}
__device__ __forceinline__ float fdec(unsigned u) {
    return (u & 0x80000000u) ? __uint_as_float(u & 0x7fffffffu)
                             : __uint_as_float(~u);
}
#define ENC_NEG_INF 0x007FFFFFu  // fenc(-inf)

// ---------------- CSR build ----------------
__global__ void k_zero_hist(int* hist) {
    int i = blockIdx.x * blockDim.x + threadIdx.x;
    if (i < NN) hist[i] = 0;
}

__global__ void k_hist(const int* __restrict__ ei, int* __restrict__ hist) {
    int e = blockIdx.x * blockDim.x + threadIdx.x;
    if (e >= ET) return;
    int d = (e < NE) ? ei[NE + e] : (e - NE);
    atomicAdd(&hist[d], 1);
}

__global__ void k_scan1(const int* __restrict__ hist, int* __restrict__ rp,
                        int* __restrict__ bsum) {
    __shared__ int sm[1024];
    int i = blockIdx.x * 1024 + threadIdx.x;
    int v = (i < NN) ? hist[i] : 0;
    sm[threadIdx.x] = v;
    __syncthreads();
    for (int off = 1; off < 1024; off <<= 1) {
        int t = (threadIdx.x >= (unsigned)off) ? sm[threadIdx.x - off] : 0;
        __syncthreads();
        sm[threadIdx.x] += t;
        __syncthreads();
    }
    if (i < NN) rp[i] = sm[threadIdx.x] - v;              // exclusive, block-local
    if (threadIdx.x == 1023) bsum[blockIdx.x] = sm[1023]; // block total
}

__global__ void k_scan2(int* __restrict__ bsum) {
    __shared__ int sm[64];
    int v = (threadIdx.x < 40) ? bsum[threadIdx.x] : 0;
    sm[threadIdx.x] = v;
    __syncthreads();
    for (int off = 1; off < 64; off <<= 1) {
        int t = (threadIdx.x >= (unsigned)off) ? sm[threadIdx.x - off] : 0;
        __syncthreads();
        sm[threadIdx.x] += t;
        __syncthreads();
    }
    if (threadIdx.x < 40) bsum[threadIdx.x] = sm[threadIdx.x] - v; // exclusive
}

__global__ void k_scan3(int* __restrict__ rp, const int* __restrict__ bsum,
                        int* __restrict__ cur) {
    int i = blockIdx.x * 1024 + threadIdx.x;
    if (i < NN) {
        int r = rp[i] + bsum[blockIdx.x];
        rp[i]  = r;
        cur[i] = r;
    }
    if (i == 0) rp[NN] = ET;
}

__global__ void k_fill(const int* __restrict__ ei, int* __restrict__ cur,
                       int* __restrict__ csrc, int* __restrict__ ceid) {
    int e = blockIdx.x * blockDim.x + threadIdx.x;
    if (e >= ET) return;
    int s, d;
    if (e < NE) { s = ei[e]; d = ei[NE + e]; }
    else        { s = d = e - NE; }
    int pos = atomicAdd(&cur[d], 1);
    csrc[pos] = s;
    ceid[pos] = e;
}

__global__ void k_dinv(const int* __restrict__ rp, float* __restrict__ dinv) {
    int i = blockIdx.x * blockDim.x + threadIdx.x;
    if (i >= NN) return;
    int deg = rp[i + 1] - rp[i];   // includes self loop -> always >= 1
    dinv[i] = rsqrtf((float)deg);
}

// ---------------- GEMM: H = act(X) @ W (+ b), M x 128 x 128 ----------------
__global__ __launch_bounds__(256)
void k_gemm(const float* __restrict__ X, const float* __restrict__ W,
            const float* __restrict__ B, float* __restrict__ H,
            int relu_in, int has_bias) {
    __shared__ float xs[64 * C];
    int tid  = threadIdx.x;
    int row0 = blockIdx.x * 64;

    // stage 64x128 X tile (apply relu on load)
    const float4* xg = (const float4*)(X + (size_t)row0 * C);
    float4* xs4 = (float4*)xs;
#pragma unroll
    for (int i = 0; i < 8; i++) {
        float4 v = xg[tid + i * 256];
        if (relu_in) {
            v.x = fmaxf(v.x, 0.f); v.y = fmaxf(v.y, 0.f);
            v.z = fmaxf(v.z, 0.f); v.w = fmaxf(v.w, 0.f);
        }
        xs4[tid + i * 256] = v;
    }
    __syncthreads();

    int cg = tid & 31;   // col group: cols [cg*4, cg*4+4)
    int rg = tid >> 5;   // row group: rows [rg*8, rg*8+8)
    float acc[8][4];
#pragma unroll
    for (int r = 0; r < 8; r++)
#pragma unroll
        for (int c = 0; c < 4; c++) acc[r][c] = 0.f;

    const float* xrow = xs + rg * 8 * C;
#pragma unroll 4
    for (int k = 0; k < C; k++) {
        float4 wv = __ldg((const float4*)(W + (size_t)k * C + cg * 4));
#pragma unroll
        for (int r = 0; r < 8; r++) {
            float xv = xrow[r * C + k];
            acc[r][0] = fmaf(xv, wv.x, acc[r][0]);
            acc[r][1] = fmaf(xv, wv.y, acc[r][1]);
            acc[r][2] = fmaf(xv, wv.z, acc[r][2]);
            acc[r][3] = fmaf(xv, wv.w, acc[r][3]);
        }
    }

    float4 bv = make_float4(0.f, 0.f, 0.f, 0.f);
    if (has_bias) bv = *(const float4*)(B + cg * 4);
#pragma unroll
    for (int r = 0; r < 8; r++) {
        float4 o;
        o.x = acc[r][0] + bv.x; o.y = acc[r][1] + bv.y;
        o.z = acc[r][2] + bv.z; o.w = acc[r][3] + bv.w;
        *(float4*)(H + (size_t)(row0 + rg * 8 + r) * C + cg * 4) = o;
    }
}

// ---------------- s[i] = H[i,:] . att ----------------
__global__ void k_rowdot(const float* __restrict__ H, const float* __restrict__ att,
                         float* __restrict__ s) {
    int warp = (blockIdx.x * blockDim.x + threadIdx.x) >> 5;
    if (warp >= NN) return;
    int lane = threadIdx.x & 31;
    float4 hv = *(const float4*)(H + (size_t)warp * C + lane * 4);
    float4 av = __ldg((const float4*)(att + lane * 4));
    float d = hv.x * av.x + hv.y * av.y + hv.z * av.z + hv.w * av.w;
#pragma unroll
    for (int o = 16; o > 0; o >>= 1) d += __shfl_xor_sync(0xffffffffu, d, o);
    if (lane == 0) s[warp] = d;
}

// ---------------- softmax-over-src passes ----------------
__global__ void k_prep(unsigned* __restrict__ m, float* __restrict__ z) {
    int i = blockIdx.x * blockDim.x + threadIdx.x;
    if (i < NN) { m[i] = ENC_NEG_INF; z[i] = 0.f; }
}

__global__ void k_e_alpha(const int* __restrict__ ei, const float* __restrict__ s,
                          float* __restrict__ alpha, unsigned* __restrict__ m) {
    int e = blockIdx.x * blockDim.x + threadIdx.x;
    if (e >= ET) return;
    int sn, dn;
    if (e < NE) { sn = ei[e]; dn = ei[NE + e]; }
    else        { sn = dn = e - NE; }
    float a = s[dn] + s[sn];
    a = (a >= 0.f) ? a : 0.2f * a;        // leaky relu
    alpha[e] = a;
    atomicMax(&m[sn], fenc(a));
}

__global__ void k_e_exp(const int* __restrict__ ei, float* __restrict__ alpha,
                        const unsigned* __restrict__ m, float* __restrict__ z) {
    int e = blockIdx.x * blockDim.x + threadIdx.x;
    if (e >= ET) return;
    int sn = (e < NE) ? ei[e] : (e - NE);
    float ex = expf(alpha[e] - fdec(m[sn]));
    alpha[e] = ex;
    atomicAdd(&z[sn], ex);
}

__global__ void k_e_div(const int* __restrict__ ei, float* __restrict__ alpha,
                        const float* __restrict__ z) {
    int e = blockIdx.x * blockDim.x + threadIdx.x;
    if (e >= ET) return;
    int sn = (e < NE) ? ei[e] : (e - NE);
    alpha[e] = alpha[e] / (z[sn] + EPS);
}

// ---------------- aggregation (gather, warp per dst row) ----------------
__global__ __launch_bounds__(256)
void k_agg_gt(const float* __restrict__ H, const int* __restrict__ rp,
              const int* __restrict__ csrc, const int* __restrict__ ceid,
              const float* __restrict__ wgt, float* __restrict__ out) {
    int node = (blockIdx.x * blockDim.x + threadIdx.x) >> 5;
    if (node >= NN) return;
    int lane = threadIdx.x & 31;
    int beg = rp[node], end = rp[node + 1];
    float ax = 0.f, ay = 0.f, az = 0.f, aw = 0.f;
    for (int p = beg; p < end; p++) {
        int sn = __ldg(&csrc[p]);
        float w = __ldg(&wgt[__ldg(&ceid[p])]);
        float4 hv = __ldg((const float4*)(H + (size_t)sn * C + lane * 4));
        ax = fmaf(w, hv.x, ax); ay = fmaf(w, hv.y, ay);
        az = fmaf(w, hv.z, az); aw = fmaf(w, hv.w, aw);
    }
    *(float4*)(out + (size_t)node * C + lane * 4) = make_float4(ax, ay, az, aw);
}

__global__ __launch_bounds__(256)
void k_agg_gcn(const float* __restrict__ H, const int* __restrict__ rp,
               const int* __restrict__ csrc, const float* __restrict__ dinv,
               float* __restrict__ out) {
    int node = (blockIdx.x * blockDim.x + threadIdx.x) >> 5;
    if (node >= NN) return;
    int lane = threadIdx.x & 31;
    int beg = rp[node], end = rp[node + 1];
    float dd = dinv[node];
    float ax = 0.f, ay = 0.f, az = 0.f, aw = 0.f;
    for (int p = beg; p < end; p++) {
        int sn = __ldg(&csrc[p]);
        float w = dd * __ldg(&dinv[sn]);
        float4 hv = __ldg((const float4*)(H + (size_t)sn * C + lane * 4));
        ax = fmaf(w, hv.x, ax); ay = fmaf(w, hv.y, ay);
        az = fmaf(w, hv.z, az); aw = fmaf(w, hv.w, aw);
    }
    *(float4*)(out + (size_t)node * C + lane * 4) = make_float4(ax, ay, az, aw);
}

// ---------------- pooling + head ----------------
__global__ void k_pool_zero(float* __restrict__ pool, float* __restrict__ cnt) {
    int i = blockIdx.x * blockDim.x + threadIdx.x;
    if (i < NG * C) pool[i] = 0.f;
    if (i < NG) cnt[i] = 0.f;
}

__global__ void k_cnt(const int* __restrict__ batch, float* __restrict__ cnt) {
    int i = blockIdx.x * blockDim.x + threadIdx.x;
    if (i < NN) atomicAdd(&cnt[batch[i]], 1.f);
}

__global__ __launch_bounds__(128)
void k_pool(const float* __restrict__ X, const int* __restrict__ batch,
            float* __restrict__ pool) {
    int c = threadIdx.x;
    int per = (NN + gridDim.x - 1) / gridDim.x;
    int n0 = blockIdx.x * per;
    int n1 = n0 + per; if (n1 > NN) n1 = NN;
    if (n0 >= n1) return;
    float acc = 0.f;
    int curg = batch[n0];
    for (int i = n0; i < n1; i++) {
        int g = batch[i];
        if (g != curg) {
            atomicAdd(&pool[(size_t)curg * C + c], acc);
            acc = 0.f; curg = g;
        }
        acc += X[(size_t)i * C + c];
    }
    atomicAdd(&pool[(size_t)curg * C + c], acc);
}

__global__ void k_head(const float* __restrict__ pool, const float* __restrict__ cnt,
                       const float* __restrict__ bg, const float* __restrict__ Wfc,
                       const float* __restrict__ bfc, float* __restrict__ out) {
    int g = blockIdx.x;
    int lane = threadIdx.x;
    float cg = fmaxf(cnt[g], 1.f);
    float logit = -INFINITY;
    if (lane < OC) {
        float acc = 0.f;
        for (int c = 0; c < C; c++) {
            float p = pool[(size_t)g * C + c] / cg + bg[c];
            acc = fmaf(p, Wfc[c * OC + lane], acc);
        }
        logit = acc + bfc[lane];
    }
    float mx = logit;
#pragma unroll
    for (int o = 16; o > 0; o >>= 1) mx = fmaxf(mx, __shfl_xor_sync(0xffffffffu, mx, o));
    float ex = (lane < OC) ? expf(logit - mx) : 0.f;
    float sm = ex;
#pragma unroll
    for (int o = 16; o > 0; o >>= 1) sm += __shfl_xor_sync(0xffffffffu, sm, o);
    if (lane < OC) out[g * OC + lane] = logit - mx - logf(sm);
}

// ---------------- host orchestration ----------------
extern "C" void kernel_launch(void* const* d_in, const int* in_sizes, int n_in,
                              void* d_out, int out_size) {
    const float* x    = (const float*)d_in[0];
    const int*   ei   = (const int*)  d_in[1];
    const int*   batch= (const int*)  d_in[2];
    const float* W1   = (const float*)d_in[3];
    const float* b1   = (const float*)d_in[4];
    const float* att1 = (const float*)d_in[5];
    const float* W2   = (const float*)d_in[6];
    const float* b2   = (const float*)d_in[7];
    const float* att2 = (const float*)d_in[8];
    const float* Wg   = (const float*)d_in[9];
    const float* bg   = (const float*)d_in[10];
    const float* Wfc  = (const float*)d_in[11];
    const float* bfc  = (const float*)d_in[12];
    float* out = (float*)d_out;

    void *ph, *pt1, *pt2, *ps, *pm, *pz, *pal, *pdi, *phist, *prp, *pcur,
         *pcs, *pce, *pbs, *ppool, *pcnt;
    cudaGetSymbolAddress(&ph,   g_h);
    cudaGetSymbolAddress(&pt1,  g_t1);
    cudaGetSymbolAddress(&pt2,  g_t2);
    cudaGetSymbolAddress(&ps,   g_s);
    cudaGetSymbolAddress(&pm,   g_m);
    cudaGetSymbolAddress(&pz,   g_z);
    cudaGetSymbolAddress(&pal,  g_alpha);
    cudaGetSymbolAddress(&pdi,  g_dinv);
    cudaGetSymbolAddress(&phist,g_hist);
    cudaGetSymbolAddress(&prp,  g_rp);
    cudaGetSymbolAddress(&pcur, g_cur);
    cudaGetSymbolAddress(&pcs,  g_csrc);
    cudaGetSymbolAddress(&pce,  g_ceid);
    cudaGetSymbolAddress(&pbs,  g_bsum);
    cudaGetSymbolAddress(&ppool,g_pool);
    cudaGetSymbolAddress(&pcnt, g_cnt);

    float* h    = (float*)ph;   float* t1 = (float*)pt1; float* t2 = (float*)pt2;
    float* s    = (float*)ps;   unsigned* m = (unsigned*)pm;
    float* z    = (float*)pz;   float* alpha = (float*)pal;
    float* dinv = (float*)pdi;  int* hist = (int*)phist;
    int* rp     = (int*)prp;    int* cur  = (int*)pcur;
    int* csrc   = (int*)pcs;    int* ceid = (int*)pce;
    int* bsum   = (int*)pbs;    float* pool = (float*)ppool;
    float* cnt  = (float*)pcnt;

    const int NBN = (NN + 255) / 256;   // 157
    const int NBE = (ET + 255) / 256;   // 2657
    const int NBW = NN / 8;             // 5000 (warp-per-node, 8 warps/block)
    const int NBG = NN / 64;            // 625 GEMM blocks

    // ---- CSR build (shared by all 3 layers) ----
    k_zero_hist<<<NBN, 256>>>(hist);
    k_hist<<<NBE, 256>>>(ei, hist);
    k_scan1<<<40, 1024>>>(hist, rp, bsum);
    k_scan2<<<1, 64>>>(bsum);
    k_scan3<<<40, 1024>>>(rp, bsum, cur);
    k_fill<<<NBE, 256>>>(ei, cur, csrc, ceid);
    k_dinv<<<NBN, 256>>>(rp, dinv);

    // ---- GT layer 1 ----
    k_gemm<<<NBG, 256>>>(x, W1, b1, h, 0, 1);
    k_rowdot<<<NBW, 256>>>(h, att1, s);
    k_prep<<<NBN, 256>>>(m, z);
    k_e_alpha<<<NBE, 256>>>(ei, s, alpha, m);
    k_e_exp<<<NBE, 256>>>(ei, alpha, m, z);
    k_e_div<<<NBE, 256>>>(ei, alpha, z);
    k_agg_gt<<<NBW, 256>>>(h, rp, csrc, ceid, alpha, t1);

    // ---- GT layer 2 (input relu'd inside gemm) ----
    k_gemm<<<NBG, 256>>>(t1, W2, b2, h, 1, 1);
    k_rowdot<<<NBW, 256>>>(h, att2, s);
    k_prep<<<NBN, 256>>>(m, z);
    k_e_alpha<<<NBE, 256>>>(ei, s, alpha, m);
    k_e_exp<<<NBE, 256>>>(ei, alpha, m, z);
    k_e_div<<<NBE, 256>>>(ei, alpha, z);
    k_agg_gt<<<NBW, 256>>>(h, rp, csrc, ceid, alpha, t2);

    // ---- GCN layer ----
    k_gemm<<<NBG, 256>>>(t2, Wg, (const float*)0, h, 1, 0);
    k_agg_gcn<<<NBW, 256>>>(h, rp, csrc, dinv, t1);

    // ---- pooling + head (bg folded into pooled mean) ----
    k_pool_zero<<<(NG * C + 255) / 256, 256>>>(pool, cnt);
    k_cnt<<<NBN, 256>>>(batch, cnt);
    k_pool<<<320, 128>>>(t1, batch, pool);
    k_head<<<NG, 32>>>(pool, cnt, bg, Wfc, bfc, out);
}

// round 3
// speedup vs baseline: 1.2708x; 1.2708x over previous
#include <cuda_runtime.h>
#include <math.h>

#define NN 40000
#define NE 640000
#define ET 680000       // NE + NN self loops
#define C  128
#define NG 64
#define OC 16
#define EPS 1e-16f

// ---------------- scratch (device globals; no allocation allowed) ----------------
__device__ float    g_h  [(size_t)NN * C];
__device__ float    g_t1 [(size_t)NN * C];
__device__ float    g_t2 [(size_t)NN * C];
__device__ float    g_s  [NN];
__device__ float    g_alpha[ET];
__device__ float    g_dinv[NN];
__device__ int      g_hist [NN];
__device__ int      g_hist2[NN];
__device__ int      g_rp  [NN + 1];
__device__ int      g_rp2 [NN + 1];
__device__ int      g_cur [NN];
__device__ int      g_cur2[NN];
__device__ int2     g_cse [ET];   // dst-CSR: {src, eid}
__device__ int2     g_cde [ET];   // src-CSR: {dst, eid}
__device__ int      g_bsum [64];
__device__ int      g_bsum2[64];
__device__ float    g_pool[NG * C];
__device__ float    g_cnt [NG];
__device__ float    g_wfrag[3 * 2 * 16384];  // [mat][hi/lo][16384] frag-ordered tf32

// ---------------- tf32 helpers ----------------
__device__ __forceinline__ unsigned f2tf(float x) {
    unsigned r;
    asm("cvt.rna.tf32.f32 %0, %1;" : "=r"(r) : "f"(x));
    return r;
}

__device__ __forceinline__ void mma_tf32(float c[4], const unsigned a[4],
                                         unsigned b0, unsigned b1) {
    asm volatile(
        "mma.sync.aligned.m16n8k8.row.col.f32.tf32.tf32.f32 "
        "{%0,%1,%2,%3}, {%4,%5,%6,%7}, {%8,%9}, {%0,%1,%2,%3};\n"
        : "+f"(c[0]), "+f"(c[1]), "+f"(c[2]), "+f"(c[3])
        : "r"(a[0]), "r"(a[1]), "r"(a[2]), "r"(a[3]), "r"(b0), "r"(b1));
}

// ---------------- init ----------------
__global__ void k_zero_all(int* hist, int* hist2, float* pool, float* cnt) {
    int i = blockIdx.x * blockDim.x + threadIdx.x;
    if (i < NN) { hist[i] = 0; hist2[i] = 0; }
    if (i < NG * C) pool[i] = 0.f;
    if (i < NG) cnt[i] = 0.f;
}

// ---------------- CSR build (both directions) ----------------
__global__ void k_hist(const int* __restrict__ ei, int* __restrict__ hist,
                       int* __restrict__ hist2) {
    int e = blockIdx.x * blockDim.x + threadIdx.x;
    if (e >= ET) return;
    int s, d;
    if (e < NE) { s = ei[e]; d = ei[NE + e]; }
    else        { s = d = e - NE; }
    atomicAdd(&hist[d], 1);
    atomicAdd(&hist2[s], 1);
}

__global__ void k_scan1(const int* __restrict__ hist, int* __restrict__ rp,
                        int* __restrict__ bsum) {
    __shared__ int sm[1024];
    int i = blockIdx.x * 1024 + threadIdx.x;
    int v = (i < NN) ? hist[i] : 0;
    sm[threadIdx.x] = v;
    __syncthreads();
    for (int off = 1; off < 1024; off <<= 1) {
        int t = (threadIdx.x >= (unsigned)off) ? sm[threadIdx.x - off] : 0;
        __syncthreads();
        sm[threadIdx.x] += t;
        __syncthreads();
    }
    if (i < NN) rp[i] = sm[threadIdx.x] - v;
    if (threadIdx.x == 1023) bsum[blockIdx.x] = sm[1023];
}

__global__ void k_scan2(int* __restrict__ bsum) {
    __shared__ int sm[64];
    int v = (threadIdx.x < 40) ? bsum[threadIdx.x] : 0;
    sm[threadIdx.x] = v;
    __syncthreads();
    for (int off = 1; off < 64; off <<= 1) {
        int t = (threadIdx.x >= (unsigned)off) ? sm[threadIdx.x - off] : 0;
        __syncthreads();
        sm[threadIdx.x] += t;
        __syncthreads();
    }
    if (threadIdx.x < 40) bsum[threadIdx.x] = sm[threadIdx.x] - v;
}

__global__ void k_scan3(int* __restrict__ rp, const int* __restrict__ bsum,
                        int* __restrict__ cur) {
    int i = blockIdx.x * 1024 + threadIdx.x;
    if (i < NN) {
        int r = rp[i] + bsum[blockIdx.x];
        rp[i]  = r;
        cur[i] = r;
    }
    if (i == 0) rp[NN] = ET;
}

__global__ void k_fill(const int* __restrict__ ei, int* __restrict__ cur,
                       int* __restrict__ cur2, int2* __restrict__ cse,
                       int2* __restrict__ cde) {
    int e = blockIdx.x * blockDim.x + threadIdx.x;
    if (e >= ET) return;
    int s, d;
    if (e < NE) { s = ei[e]; d = ei[NE + e]; }
    else        { s = d = e - NE; }
    int pos = atomicAdd(&cur[d], 1);
    cse[pos] = make_int2(s, e);
    int pos2 = atomicAdd(&cur2[s], 1);
    cde[pos2] = make_int2(d, e);
}

__global__ void k_dinv(const int* __restrict__ rp, float* __restrict__ dinv) {
    int i = blockIdx.x * blockDim.x + threadIdx.x;
    if (i >= NN) return;
    int deg = rp[i + 1] - rp[i];   // includes self loop -> always >= 1
    dinv[i] = rsqrtf((float)deg);
}

// ---------------- weight prep: split W into tf32 hi/lo, frag-swizzled ----------------
// frag index f = (kk*16 + t)*32 + lane; b0 = W[kk*8+tig][t*8+grp], b1 = W[kk*8+tig+4][t*8+grp]
__global__ void k_wprep(const float* __restrict__ W1, const float* __restrict__ W2,
                        const float* __restrict__ Wg, float* __restrict__ wfrag) {
    int idx = blockIdx.x * blockDim.x + threadIdx.x;
    if (idx >= 3 * 8192) return;
    int mat = idx >> 13;
    int f   = idx & 8191;
    const float* W = (mat == 0) ? W1 : ((mat == 1) ? W2 : Wg);
    int lane = f & 31, t = (f >> 5) & 15, kk = f >> 9;
    int tig = lane & 3, grp = lane >> 2;
    int colN = t * 8 + grp;
    float x0 = W[(kk * 8 + tig) * C + colN];
    float x1 = W[(kk * 8 + tig + 4) * C + colN];
    float* whi = wfrag + (size_t)mat * 32768;
    float* wlo = whi + 16384;
    unsigned h0 = f2tf(x0); float l0 = x0 - __uint_as_float(h0);
    unsigned h1 = f2tf(x1); float l1 = x1 - __uint_as_float(h1);
    whi[f * 2]     = __uint_as_float(h0);
    whi[f * 2 + 1] = __uint_as_float(h1);
    wlo[f * 2]     = __uint_as_float(f2tf(l0));
    wlo[f * 2 + 1] = __uint_as_float(f2tf(l1));
}

// ---------------- GEMM: H = act(X) @ W (+ b) via tf32 tensor cores ----------------
// BM=64, BN=128(full), K=128(full). 256 threads = 8 warps: 4(m) x 2(n), warp tile 16x64.
#define GEMM_SMEM_FLOATS (64 * 132 * 2 + 32768)
#define GEMM_SMEM_BYTES  (GEMM_SMEM_FLOATS * 4)

__global__ __launch_bounds__(256)
void k_gemm_tc(const float* __restrict__ X, const float* __restrict__ wfrag,
               const float* __restrict__ Bb, float* __restrict__ H,
               int relu_in, int has_bias) {
    extern __shared__ float smf[];
    float* Xh = smf;                     // [64][132] tf32-hi bit patterns
    float* Xl = smf + 64 * 132;          // [64][132] tf32-lo
    float* Wh = smf + 2 * 64 * 132;      // [16384]  frag-ordered
    float* Wl = Wh + 16384;

    int tid  = threadIdx.x;
    int row0 = blockIdx.x * 64;

    // stage X tile, split hi/lo
    const float4* xg = (const float4*)(X + (size_t)row0 * C);
#pragma unroll
    for (int i = 0; i < 8; i++) {
        int idx = tid + i * 256;              // 2048 float4 = 64 rows x 32
        float4 v = xg[idx];
        if (relu_in) {
            v.x = fmaxf(v.x, 0.f); v.y = fmaxf(v.y, 0.f);
            v.z = fmaxf(v.z, 0.f); v.w = fmaxf(v.w, 0.f);
        }
        int r  = idx >> 5;
        int c0 = (idx & 31) * 4;
        float xv[4] = {v.x, v.y, v.z, v.w};
#pragma unroll
        for (int j = 0; j < 4; j++) {
            unsigned hi = f2tf(xv[j]);
            float lo = xv[j] - __uint_as_float(hi);
            Xh[r * 132 + c0 + j] = __uint_as_float(hi);
            Xl[r * 132 + c0 + j] = __uint_as_float(f2tf(lo));
        }
    }
    // stage W frags (hi+lo contiguous: 32768 floats = 8192 float4)
    {
        const float4* wg = (const float4*)wfrag;
        float4* ws = (float4*)Wh;
#pragma unroll
        for (int i = tid; i < 8192; i += 256) ws[i] = wg[i];
    }
    __syncthreads();

    int wid = tid >> 5, lane = tid & 31;
    int mw = wid >> 1, nw = wid & 1;
    int m0 = mw * 16;          // warp row offset
    int t0 = nw * 8;           // warp ntile offset (8 ntiles of 8 cols)
    int grp = lane >> 2, tig = lane & 3;

    float acc[8][4];
#pragma unroll
    for (int t = 0; t < 8; t++)
#pragma unroll
        for (int j = 0; j < 4; j++) acc[t][j] = 0.f;

#pragma unroll
    for (int kk = 0; kk < 16; kk++) {
        int arow = m0 + grp;
        int acol = kk * 8 + tig;
        unsigned ah[4], al[4];
        ah[0] = __float_as_uint(Xh[arow * 132 + acol]);
        ah[1] = __float_as_uint(Xh[(arow + 8) * 132 + acol]);
        ah[2] = __float_as_uint(Xh[arow * 132 + acol + 4]);
        ah[3] = __float_as_uint(Xh[(arow + 8) * 132 + acol + 4]);
        al[0] = __float_as_uint(Xl[arow * 132 + acol]);
        al[1] = __float_as_uint(Xl[(arow + 8) * 132 + acol]);
        al[2] = __float_as_uint(Xl[arow * 132 + acol + 4]);
        al[3] = __float_as_uint(Xl[(arow + 8) * 132 + acol + 4]);
#pragma unroll
        for (int t = 0; t < 8; t++) {
            int f = (kk * 16 + (t0 + t)) * 32 + lane;
            uint2 bh = *(const uint2*)(Wh + f * 2);
            uint2 bl = *(const uint2*)(Wl + f * 2);
            mma_tf32(acc[t], ah, bh.x, bh.y);   // hi*hi
            mma_tf32(acc[t], al, bh.x, bh.y);   // lo*hi
            mma_tf32(acc[t], ah, bl.x, bl.y);   // hi*lo
        }
    }

    // epilogue
#pragma unroll
    for (int t = 0; t < 8; t++) {
        int col = (t0 + t) * 8 + tig * 2;
        float2 bv = make_float2(0.f, 0.f);
        if (has_bias) bv = *(const float2*)(Bb + col);
        int row = row0 + m0 + grp;
        float2 o0 = make_float2(acc[t][0] + bv.x, acc[t][1] + bv.y);
        float2 o1 = make_float2(acc[t][2] + bv.x, acc[t][3] + bv.y);
        *(float2*)(H + (size_t)row * C + col)       = o0;
        *(float2*)(H + (size_t)(row + 8) * C + col) = o1;
    }
}

// ---------------- s[i] = H[i,:] . att ----------------
__global__ void k_rowdot(const float* __restrict__ H, const float* __restrict__ att,
                         float* __restrict__ s) {
    int warp = (blockIdx.x * blockDim.x + threadIdx.x) >> 5;
    if (warp >= NN) return;
    int lane = threadIdx.x & 31;
    float4 hv = *(const float4*)(H + (size_t)warp * C + lane * 4);
    float4 av = __ldg((const float4*)(att + lane * 4));
    float d = hv.x * av.x + hv.y * av.y + hv.z * av.z + hv.w * av.w;
#pragma unroll
    for (int o = 16; o > 0; o >>= 1) d += __shfl_xor_sync(0xffffffffu, d, o);
    if (lane == 0) s[warp] = d;
}

// ---------------- fused softmax over src groups (warp per src node) ----------------
__global__ __launch_bounds__(256)
void k_softmax(const int* __restrict__ rp2, const int2* __restrict__ cde,
               const float* __restrict__ s, float* __restrict__ alpha) {
    int node = (blockIdx.x * blockDim.x + threadIdx.x) >> 5;
    if (node >= NN) return;
    int lane = threadIdx.x & 31;
    int beg = rp2[node], end = rp2[node + 1];
    int deg = end - beg;
    float sv = s[node];

    if (deg <= 128) {
        float ex[4];
        int   eid[4];
        int k = 0;
        float mx = -INFINITY;
        for (int p = beg + lane; p < end; p += 32, k++) {
            int2 de = __ldg(&cde[p]);
            float a = sv + __ldg(&s[de.x]);
            a = (a >= 0.f) ? a : 0.2f * a;
            ex[k] = a; eid[k] = de.y;
            mx = fmaxf(mx, a);
        }
#pragma unroll
        for (int o = 16; o > 0; o >>= 1) mx = fmaxf(mx, __shfl_xor_sync(0xffffffffu, mx, o));
        float sum = 0.f;
#pragma unroll
        for (int i = 0; i < 4; i++) {
            if (i < k) { ex[i] = expf(ex[i] - mx); sum += ex[i]; }
        }
#pragma unroll
        for (int o = 16; o > 0; o >>= 1) sum += __shfl_xor_sync(0xffffffffu, sum, o);
        float inv = 1.f / (sum + EPS);
#pragma unroll
        for (int i = 0; i < 4; i++) {
            if (i < k) alpha[eid[i]] = ex[i] * inv;
        }
    } else {
        // fallback (essentially never taken for this graph distribution)
        float mx = -INFINITY;
        for (int p = beg + lane; p < end; p += 32) {
            int2 de = cde[p];
            float a = sv + s[de.x];
            a = (a >= 0.f) ? a : 0.2f * a;
            mx = fmaxf(mx, a);
        }
#pragma unroll
        for (int o = 16; o > 0; o >>= 1) mx = fmaxf(mx, __shfl_xor_sync(0xffffffffu, mx, o));
        float sum = 0.f;
        for (int p = beg + lane; p < end; p += 32) {
            int2 de = cde[p];
            float a = sv + s[de.x];
            a = (a >= 0.f) ? a : 0.2f * a;
            sum += expf(a - mx);
        }
#pragma unroll
        for (int o = 16; o > 0; o >>= 1) sum += __shfl_xor_sync(0xffffffffu, sum, o);
        float inv = 1.f / (sum + EPS);
        for (int p = beg + lane; p < end; p += 32) {
            int2 de = cde[p];
            float a = sv + s[de.x];
            a = (a >= 0.f) ? a : 0.2f * a;
            alpha[de.y] = expf(a - mx) * inv;
        }
    }
}

// ---------------- aggregation (gather, warp per dst row) ----------------
__global__ __launch_bounds__(256)
void k_agg_gt(const float* __restrict__ H, const int* __restrict__ rp,
              const int2* __restrict__ cse, const float* __restrict__ wgt,
              float* __restrict__ out) {
    int node = (blockIdx.x * blockDim.x + threadIdx.x) >> 5;
    if (node >= NN) return;
    int lane = threadIdx.x & 31;
    int beg = rp[node], end = rp[node + 1];
    float ax = 0.f, ay = 0.f, az = 0.f, aw = 0.f;
    for (int p = beg; p < end; p++) {
        int2 se = __ldg(&cse[p]);
        float w = __ldg(&wgt[se.y]);
        float4 hv = __ldg((const float4*)(H + (size_t)se.x * C + lane * 4));
        ax = fmaf(w, hv.x, ax); ay = fmaf(w, hv.y, ay);
        az = fmaf(w, hv.z, az); aw = fmaf(w, hv.w, aw);
    }
    *(float4*)(out + (size_t)node * C + lane * 4) = make_float4(ax, ay, az, aw);
}

__global__ __launch_bounds__(256)
void k_agg_gcn(const float* __restrict__ H, const int* __restrict__ rp,
               const int2* __restrict__ cse, const float* __restrict__ dinv,
               float* __restrict__ out) {
    int node = (blockIdx.x * blockDim.x + threadIdx.x) >> 5;
    if (node >= NN) return;
    int lane = threadIdx.x & 31;
    int beg = rp[node], end = rp[node + 1];
    float dd = dinv[node];
    float ax = 0.f, ay = 0.f, az = 0.f, aw = 0.f;
    for (int p = beg; p < end; p++) {
        int2 se = __ldg(&cse[p]);
        float w = dd * __ldg(&dinv[se.x]);
        float4 hv = __ldg((const float4*)(H + (size_t)se.x * C + lane * 4));
        ax = fmaf(w, hv.x, ax); ay = fmaf(w, hv.y, ay);
        az = fmaf(w, hv.z, az); aw = fmaf(w, hv.w, aw);
    }
    *(float4*)(out + (size_t)node * C + lane * 4) = make_float4(ax, ay, az, aw);
}

// ---------------- pooling + head ----------------
__global__ void k_cnt(const int* __restrict__ batch, float* __restrict__ cnt) {
    int i = blockIdx.x * blockDim.x + threadIdx.x;
    if (i < NN) atomicAdd(&cnt[batch[i]], 1.f);
}

__global__ __launch_bounds__(128)
void k_pool(const float* __restrict__ X, const int* __restrict__ batch,
            float* __restrict__ pool) {
    int c = threadIdx.x;
    int per = (NN + gridDim.x - 1) / gridDim.x;
    int n0 = blockIdx.x * per;
    int n1 = n0 + per; if (n1 > NN) n1 = NN;
    if (n0 >= n1) return;
    float acc = 0.f;
    int curg = batch[n0];
    for (int i = n0; i < n1; i++) {
        int g = batch[i];
        if (g != curg) {
            atomicAdd(&pool[(size_t)curg * C + c], acc);
            acc = 0.f; curg = g;
        }
        acc += X[(size_t)i * C + c];
    }
    atomicAdd(&pool[(size_t)curg * C + c], acc);
}

__global__ void k_head(const float* __restrict__ pool, const float* __restrict__ cnt,
                       const float* __restrict__ bg, const float* __restrict__ Wfc,
                       const float* __restrict__ bfc, float* __restrict__ out) {
    int g = blockIdx.x;
    int lane = threadIdx.x;
    float cg = fmaxf(cnt[g], 1.f);
    float logit = -INFINITY;
    if (lane < OC) {
        float acc = 0.f;
        for (int c = 0; c < C; c++) {
            float p = pool[(size_t)g * C + c] / cg + bg[c];
            acc = fmaf(p, Wfc[c * OC + lane], acc);
        }
        logit = acc + bfc[lane];
    }
    float mx = logit;
#pragma unroll
    for (int o = 16; o > 0; o >>= 1) mx = fmaxf(mx, __shfl_xor_sync(0xffffffffu, mx, o));
    float ex = (lane < OC) ? expf(logit - mx) : 0.f;
    float sm = ex;
#pragma unroll
    for (int o = 16; o > 0; o >>= 1) sm += __shfl_xor_sync(0xffffffffu, sm, o);
    if (lane < OC) out[g * OC + lane] = logit - mx - logf(sm);
}

// ---------------- host orchestration ----------------
extern "C" void kernel_launch(void* const* d_in, const int* in_sizes, int n_in,
                              void* d_out, int out_size) {
    const float* x    = (const float*)d_in[0];
    const int*   ei   = (const int*)  d_in[1];
    const int*   batch= (const int*)  d_in[2];
    const float* W1   = (const float*)d_in[3];
    const float* b1   = (const float*)d_in[4];
    const float* att1 = (const float*)d_in[5];
    const float* W2   = (const float*)d_in[6];
    const float* b2   = (const float*)d_in[7];
    const float* att2 = (const float*)d_in[8];
    const float* Wg   = (const float*)d_in[9];
    const float* bg   = (const float*)d_in[10];
    const float* Wfc  = (const float*)d_in[11];
    const float* bfc  = (const float*)d_in[12];
    float* out = (float*)d_out;

    void *ph, *pt1, *pt2, *ps, *pal, *pdi, *phist, *phist2, *prp, *prp2,
         *pcur, *pcur2, *pcse, *pcde, *pbs, *pbs2, *ppool, *pcnt, *pwf;
    cudaGetSymbolAddress(&ph,    g_h);
    cudaGetSymbolAddress(&pt1,   g_t1);
    cudaGetSymbolAddress(&pt2,   g_t2);
    cudaGetSymbolAddress(&ps,    g_s);
    cudaGetSymbolAddress(&pal,   g_alpha);
    cudaGetSymbolAddress(&pdi,   g_dinv);
    cudaGetSymbolAddress(&phist, g_hist);
    cudaGetSymbolAddress(&phist2,g_hist2);
    cudaGetSymbolAddress(&prp,   g_rp);
    cudaGetSymbolAddress(&prp2,  g_rp2);
    cudaGetSymbolAddress(&pcur,  g_cur);
    cudaGetSymbolAddress(&pcur2, g_cur2);
    cudaGetSymbolAddress(&pcse,  g_cse);
    cudaGetSymbolAddress(&pcde,  g_cde);
    cudaGetSymbolAddress(&pbs,   g_bsum);
    cudaGetSymbolAddress(&pbs2,  g_bsum2);
    cudaGetSymbolAddress(&ppool, g_pool);
    cudaGetSymbolAddress(&pcnt,  g_cnt);
    cudaGetSymbolAddress(&pwf,   g_wfrag);

    float* h     = (float*)ph;    float* t1   = (float*)pt1;
    float* t2    = (float*)pt2;   float* s    = (float*)ps;
    float* alpha = (float*)pal;   float* dinv = (float*)pdi;
    int* hist    = (int*)phist;   int* hist2  = (int*)phist2;
    int* rp      = (int*)prp;     int* rp2    = (int*)prp2;
    int* cur     = (int*)pcur;    int* cur2   = (int*)pcur2;
    int2* cse    = (int2*)pcse;   int2* cde   = (int2*)pcde;
    int* bsum    = (int*)pbs;     int* bsum2  = (int*)pbs2;
    float* pool  = (float*)ppool; float* cnt  = (float*)pcnt;
    float* wfrag = (float*)pwf;

    cudaFuncSetAttribute(k_gemm_tc, cudaFuncAttributeMaxDynamicSharedMemorySize,
                         GEMM_SMEM_BYTES);

    const int NBN = (NN + 255) / 256;   // 157
    const int NBE = (ET + 255) / 256;   // 2657
    const int NBW = NN / 8;             // 5000 warp-per-node blocks
    const int NBG = NN / 64;            // 625 GEMM blocks

    // ---- init + CSR build (both directions) + weight prep ----
    k_zero_all<<<NBN, 256>>>(hist, hist2, pool, cnt);
    k_wprep<<<96, 256>>>(W1, W2, Wg, wfrag);
    k_hist<<<NBE, 256>>>(ei, hist, hist2);
    k_scan1<<<40, 1024>>>(hist, rp, bsum);
    k_scan2<<<1, 64>>>(bsum);
    k_scan3<<<40, 1024>>>(rp, bsum, cur);
    k_scan1<<<40, 1024>>>(hist2, rp2, bsum2);
    k_scan2<<<1, 64>>>(bsum2);
    k_scan3<<<40, 1024>>>(rp2, bsum2, cur2);
    k_fill<<<NBE, 256>>>(ei, cur, cur2, cse, cde);
    k_dinv<<<NBN, 256>>>(rp, dinv);

    // ---- GT layer 1 ----
    k_gemm_tc<<<NBG, 256, GEMM_SMEM_BYTES>>>(x, wfrag, b1, h, 0, 1);
    k_rowdot<<<NBW, 256>>>(h, att1, s);
    k_softmax<<<NBW, 256>>>(rp2, cde, s, alpha);
    k_agg_gt<<<NBW, 256>>>(h, rp, cse, alpha, t1);

    // ---- GT layer 2 (input relu'd inside gemm) ----
    k_gemm_tc<<<NBG, 256, GEMM_SMEM_BYTES>>>(t1, wfrag + 32768, b2, h, 1, 1);
    k_rowdot<<<NBW, 256>>>(h, att2, s);
    k_softmax<<<NBW, 256>>>(rp2, cde, s, alpha);
    k_agg_gt<<<NBW, 256>>>(h, rp, cse, alpha, t2);

    // ---- GCN layer ----
    k_gemm_tc<<<NBG, 256, GEMM_SMEM_BYTES>>>(t2, wfrag + 65536, (const float*)0, h, 1, 0);
    k_agg_gcn<<<NBW, 256>>>(h, rp, cse, dinv, t1);

    // ---- pooling + head (bg folded into pooled mean) ----
    k_cnt<<<NBN, 256>>>(batch, cnt);
    k_pool<<<320, 128>>>(t1, batch, pool);
    k_head<<<NG, 32>>>(pool, cnt, bg, Wfc, bfc, out);
}

// round 4
// speedup vs baseline: 1.3400x; 1.0544x over previous
#include <cuda_runtime.h>
#include <math.h>

#define NN 40000
#define NE 640000
#define ET 680000       // NE + NN self loops
#define C  128
#define NG 64
#define OC 16
#define EPS 1e-16f

// ---------------- scratch (device globals; no allocation allowed) ----------------
__device__ float    g_h  [(size_t)NN * C];
__device__ float    g_t1 [(size_t)NN * C];
__device__ float    g_t2 [(size_t)NN * C];
__device__ float    g_s  [NN];
__device__ float    g_alpha[ET];
__device__ float    g_dinv[NN];
__device__ int      g_hist [NN];
__device__ int      g_hist2[NN];
__device__ int      g_rp  [NN + 1];
__device__ int      g_rp2 [NN + 1];
__device__ int      g_cur [NN];
__device__ int      g_cur2[NN];
__device__ int      g_cse [ET];   // dst-CSR: src node per slot
__device__ int2     g_cde [ET];   // src-CSR: {dst node, dst-CSR slot}
__device__ int      g_bsum [64];
__device__ int      g_bsum2[64];
__device__ float    g_pool[NG * C];
__device__ float    g_cnt [NG];
__device__ float    g_wfrag[3 * 2 * 16384];  // [mat][hi/lo][16384] frag-ordered tf32

// ---------------- tf32 helpers ----------------
__device__ __forceinline__ unsigned f2tf(float x) {
    unsigned r;
    asm("cvt.rna.tf32.f32 %0, %1;" : "=r"(r) : "f"(x));
    return r;
}

__device__ __forceinline__ void mma_tf32(float c[4], const unsigned a[4],
                                         unsigned b0, unsigned b1) {
    asm volatile(
        "mma.sync.aligned.m16n8k8.row.col.f32.tf32.tf32.f32 "
        "{%0,%1,%2,%3}, {%4,%5,%6,%7}, {%8,%9}, {%0,%1,%2,%3};\n"
        : "+f"(c[0]), "+f"(c[1]), "+f"(c[2]), "+f"(c[3])
        : "r"(a[0]), "r"(a[1]), "r"(a[2]), "r"(a[3]), "r"(b0), "r"(b1));
}

// ---------------- init ----------------
__global__ void k_zero_all(int* hist, int* hist2, float* pool, float* cnt) {
    int i = blockIdx.x * blockDim.x + threadIdx.x;
    if (i < NN) { hist[i] = 0; hist2[i] = 0; }
    if (i < NG * C) pool[i] = 0.f;
    if (i < NG) cnt[i] = 0.f;
}

// ---------------- CSR build (both directions) ----------------
__global__ void k_hist(const int* __restrict__ ei, int* __restrict__ hist,
                       int* __restrict__ hist2) {
    int e = blockIdx.x * blockDim.x + threadIdx.x;
    if (e >= ET) return;
    int s, d;
    if (e < NE) { s = ei[e]; d = ei[NE + e]; }
    else        { s = d = e - NE; }
    atomicAdd(&hist[d], 1);
    atomicAdd(&hist2[s], 1);
}

// dual-direction block scan (blocks 0..39 -> dir0, 40..79 -> dir1)
__global__ __launch_bounds__(1024)
void k_scan1f(const int* __restrict__ hist, const int* __restrict__ hist2,
              int* __restrict__ rp, int* __restrict__ rp2,
              int* __restrict__ bsum, int* __restrict__ bsum2) {
    __shared__ int wsum[32];
    int dir = (blockIdx.x >= 40);
    int blk = blockIdx.x - dir * 40;
    const int* in = dir ? hist2 : hist;
    int* rpo = dir ? rp2 : rp;
    int* bso = dir ? bsum2 : bsum;

    int i = blk * 1024 + threadIdx.x;
    int v = (i < NN) ? in[i] : 0;
    int lane = threadIdx.x & 31, w = threadIdx.x >> 5;
    int inc = v;
#pragma unroll
    for (int off = 1; off < 32; off <<= 1) {
        int t = __shfl_up_sync(0xffffffffu, inc, off);
        if (lane >= off) inc += t;
    }
    if (lane == 31) wsum[w] = inc;
    __syncthreads();
    if (w == 0) {
        int x = wsum[lane];
#pragma unroll
        for (int off = 1; off < 32; off <<= 1) {
            int t = __shfl_up_sync(0xffffffffu, x, off);
            if (lane >= off) x += t;
        }
        wsum[lane] = x;
    }
    __syncthreads();
    int wpre = (w > 0) ? wsum[w - 1] : 0;
    if (i < NN) rpo[i] = wpre + inc - v;
    if (threadIdx.x == 1023) bso[blk] = wpre + inc;
}

__global__ void k_scan2f(int* __restrict__ bsum, int* __restrict__ bsum2) {
    __shared__ int sm[128];
    int tid = threadIdx.x;
    int half = tid >> 6, idx = tid & 63;
    int* bs = half ? bsum2 : bsum;
    int v = (idx < 40) ? bs[idx] : 0;
    sm[tid] = v;
    __syncthreads();
    for (int off = 1; off < 64; off <<= 1) {
        int t = (idx >= off) ? sm[tid - off] : 0;
        __syncthreads();
        sm[tid] += t;
        __syncthreads();
    }
    if (idx < 40) bs[idx] = sm[tid] - v;
}

__global__ __launch_bounds__(1024)
void k_scan3f(int* __restrict__ rp, int* __restrict__ rp2,
              const int* __restrict__ bsum, const int* __restrict__ bsum2,
              int* __restrict__ cur, int* __restrict__ cur2) {
    int dir = (blockIdx.x >= 40);
    int blk = blockIdx.x - dir * 40;
    int* rpo  = dir ? rp2  : rp;
    int* curo = dir ? cur2 : cur;
    const int* bso = dir ? bsum2 : bsum;
    int i = blk * 1024 + threadIdx.x;
    if (i < NN) {
        int r = rpo[i] + bso[blk];
        rpo[i]  = r;
        curo[i] = r;
    }
    if (blk == 0 && threadIdx.x == 0) rpo[NN] = ET;
}

__global__ void k_fill(const int* __restrict__ ei, int* __restrict__ cur,
                       int* __restrict__ cur2, int* __restrict__ cse,
                       int2* __restrict__ cde) {
    int e = blockIdx.x * blockDim.x + threadIdx.x;
    if (e >= ET) return;
    int s, d;
    if (e < NE) { s = ei[e]; d = ei[NE + e]; }
    else        { s = d = e - NE; }
    int pos = atomicAdd(&cur[d], 1);
    cse[pos] = s;
    int pos2 = atomicAdd(&cur2[s], 1);
    cde[pos2] = make_int2(d, pos);
}

__global__ void k_dinv(const int* __restrict__ rp, float* __restrict__ dinv) {
    int i = blockIdx.x * blockDim.x + threadIdx.x;
    if (i >= NN) return;
    int deg = rp[i + 1] - rp[i];   // includes self loop -> always >= 1
    dinv[i] = rsqrtf((float)deg);
}

// ---------------- weight prep: split W into tf32 hi/lo, frag-swizzled ----------------
// frag f = (kk*16 + t)*32 + lane; b0 = W[kk*8+tig][t*8+grp], b1 = W[kk*8+tig+4][t*8+grp]
__global__ void k_wprep(const float* __restrict__ W1, const float* __restrict__ W2,
                        const float* __restrict__ Wg, float* __restrict__ wfrag) {
    int idx = blockIdx.x * blockDim.x + threadIdx.x;
    if (idx >= 3 * 8192) return;
    int mat = idx >> 13;
    int f   = idx & 8191;
    const float* W = (mat == 0) ? W1 : ((mat == 1) ? W2 : Wg);
    int lane = f & 31, t = (f >> 5) & 15, kk = f >> 9;
    int tig = lane & 3, grp = lane >> 2;
    int colN = t * 8 + grp;
    float x0 = W[(kk * 8 + tig) * C + colN];
    float x1 = W[(kk * 8 + tig + 4) * C + colN];
    float* whi = wfrag + (size_t)mat * 32768;
    float* wlo = whi + 16384;
    unsigned h0 = f2tf(x0); float l0 = x0 - __uint_as_float(h0);
    unsigned h1 = f2tf(x1); float l1 = x1 - __uint_as_float(h1);
    whi[f * 2]     = __uint_as_float(h0);
    whi[f * 2 + 1] = __uint_as_float(h1);
    wlo[f * 2]     = __uint_as_float(f2tf(l0));
    wlo[f * 2 + 1] = __uint_as_float(f2tf(l1));
}

// ---------------- GEMM + fused rowdot ----------------
// BM=64, BN=128, K=128. 8 warps: 2(m) x 4(n), warp tile 32x32.
#define GEMM_SMEM_FLOATS (64 * 132 * 2 + 32768)
#define GEMM_SMEM_BYTES  (GEMM_SMEM_FLOATS * 4)

__global__ __launch_bounds__(256)
void k_gemm_tc(const float* __restrict__ X, const float* __restrict__ wfrag,
               const float* __restrict__ Bb, const float* __restrict__ att,
               float* __restrict__ H, float* __restrict__ sOut,
               int relu_in, int has_bias) {
    extern __shared__ float smf[];
    float* Xh = smf;                     // [64][132] tf32-hi
    float* Xl = smf + 64 * 132;          // [64][132] tf32-lo
    float* Wh = smf + 2 * 64 * 132;      // [16384] frag-ordered
    float* Wl = Wh + 16384;

    int tid  = threadIdx.x;
    int row0 = blockIdx.x * 64;

    // stage X tile, split hi/lo
    const float4* xg = (const float4*)(X + (size_t)row0 * C);
#pragma unroll
    for (int i = 0; i < 8; i++) {
        int idx = tid + i * 256;              // 2048 float4 = 64 rows x 32
        float4 v = xg[idx];
        if (relu_in) {
            v.x = fmaxf(v.x, 0.f); v.y = fmaxf(v.y, 0.f);
            v.z = fmaxf(v.z, 0.f); v.w = fmaxf(v.w, 0.f);
        }
        int r  = idx >> 5;
        int c0 = (idx & 31) * 4;
        float xv[4] = {v.x, v.y, v.z, v.w};
#pragma unroll
        for (int j = 0; j < 4; j++) {
            unsigned hi = f2tf(xv[j]);
            float lo = xv[j] - __uint_as_float(hi);
            Xh[r * 132 + c0 + j] = __uint_as_float(hi);
            Xl[r * 132 + c0 + j] = __uint_as_float(f2tf(lo));
        }
    }
    // stage W frags
    {
        const float4* wg = (const float4*)wfrag;
        float4* ws = (float4*)Wh;
#pragma unroll
        for (int i = tid; i < 8192; i += 256) ws[i] = wg[i];
    }
    __syncthreads();

    int wid = tid >> 5, lane = tid & 31;
    int mw = wid & 1, nw = wid >> 1;
    int m0  = mw * 32;         // warp rows [m0, m0+32)
    int n0g = nw * 4;          // warp ntiles [n0g, n0g+4) (8 cols each)
    int grp = lane >> 2, tig = lane & 3;

    float acc[2][4][4];
#pragma unroll
    for (int ms = 0; ms < 2; ms++)
#pragma unroll
        for (int t = 0; t < 4; t++)
#pragma unroll
            for (int j = 0; j < 4; j++) acc[ms][t][j] = 0.f;

#pragma unroll
    for (int kk = 0; kk < 16; kk++) {
        unsigned ah[2][4], al[2][4];
#pragma unroll
        for (int ms = 0; ms < 2; ms++) {
            int ar = m0 + ms * 16 + grp;
            int ac = kk * 8 + tig;
            ah[ms][0] = __float_as_uint(Xh[ar * 132 + ac]);
            ah[ms][1] = __float_as_uint(Xh[(ar + 8) * 132 + ac]);
            ah[ms][2] = __float_as_uint(Xh[ar * 132 + ac + 4]);
            ah[ms][3] = __float_as_uint(Xh[(ar + 8) * 132 + ac + 4]);
            al[ms][0] = __float_as_uint(Xl[ar * 132 + ac]);
            al[ms][1] = __float_as_uint(Xl[(ar + 8) * 132 + ac]);
            al[ms][2] = __float_as_uint(Xl[ar * 132 + ac + 4]);
            al[ms][3] = __float_as_uint(Xl[(ar + 8) * 132 + ac + 4]);
        }
#pragma unroll
        for (int t = 0; t < 4; t++) {
            int f = (kk * 16 + n0g + t) * 32 + lane;
            uint2 bh = *(const uint2*)(Wh + f * 2);
            uint2 bl = *(const uint2*)(Wl + f * 2);
#pragma unroll
            for (int ms = 0; ms < 2; ms++) {
                mma_tf32(acc[ms][t], ah[ms], bh.x, bh.y);   // hi*hi
                mma_tf32(acc[ms][t], al[ms], bh.x, bh.y);   // lo*hi
                mma_tf32(acc[ms][t], ah[ms], bl.x, bl.y);   // hi*lo
            }
        }
    }

    // epilogue: bias add, H store, fused att rowdot
    float part[4] = {0.f, 0.f, 0.f, 0.f};  // rows m0+grp, +8, +16, +24
    bool do_dot = (att != 0);
#pragma unroll
    for (int t = 0; t < 4; t++) {
        int col = (n0g + t) * 8 + tig * 2;
        float2 bv = make_float2(0.f, 0.f);
        if (has_bias) bv = *(const float2*)(Bb + col);
        float2 av = make_float2(0.f, 0.f);
        if (do_dot) av = __ldg((const float2*)(att + col));
#pragma unroll
        for (int ms = 0; ms < 2; ms++) {
            int row = row0 + m0 + ms * 16 + grp;
            float o0 = acc[ms][t][0] + bv.x, o1 = acc[ms][t][1] + bv.y;
            float o2 = acc[ms][t][2] + bv.x, o3 = acc[ms][t][3] + bv.y;
            *(float2*)(H + (size_t)row * C + col)       = make_float2(o0, o1);
            *(float2*)(H + (size_t)(row + 8) * C + col) = make_float2(o2, o3);
            part[ms * 2]     += o0 * av.x + o1 * av.y;
            part[ms * 2 + 1] += o2 * av.x + o3 * av.y;
        }
    }
    if (do_dot) {
        __syncthreads();                 // everyone done reading Xh
        float* sarr = smf;               // reuse
        if (tid < 64) sarr[tid] = 0.f;
        __syncthreads();
        atomicAdd(&sarr[m0 + grp],      part[0]);
        atomicAdd(&sarr[m0 + grp + 8],  part[1]);
        atomicAdd(&sarr[m0 + grp + 16], part[2]);
        atomicAdd(&sarr[m0 + grp + 24], part[3]);
        __syncthreads();
        if (tid < 64) sOut[row0 + tid] = sarr[tid];
    }
}

// ---------------- fused softmax over src groups (warp per src node) ----------------
__global__ __launch_bounds__(256)
void k_softmax(const int* __restrict__ rp2, const int2* __restrict__ cde,
               const float* __restrict__ s, float* __restrict__ alpha) {
    int node = (blockIdx.x * blockDim.x + threadIdx.x) >> 5;
    if (node >= NN) return;
    int lane = threadIdx.x & 31;
    int beg = rp2[node], end = rp2[node + 1];
    int deg = end - beg;
    float sv = s[node];

    if (deg <= 128) {
        float ex[4];
        int   slot[4];
        int k = 0;
        float mx = -INFINITY;
        for (int p = beg + lane; p < end; p += 32, k++) {
            int2 de = __ldg(&cde[p]);
            float a = sv + __ldg(&s[de.x]);
            a = (a >= 0.f) ? a : 0.2f * a;
            ex[k] = a; slot[k] = de.y;
            mx = fmaxf(mx, a);
        }
#pragma unroll
        for (int o = 16; o > 0; o >>= 1) mx = fmaxf(mx, __shfl_xor_sync(0xffffffffu, mx, o));
        float sum = 0.f;
#pragma unroll
        for (int i = 0; i < 4; i++) {
            if (i < k) { ex[i] = expf(ex[i] - mx); sum += ex[i]; }
        }
#pragma unroll
        for (int o = 16; o > 0; o >>= 1) sum += __shfl_xor_sync(0xffffffffu, sum, o);
        float inv = 1.f / (sum + EPS);
#pragma unroll
        for (int i = 0; i < 4; i++) {
            if (i < k) alpha[slot[i]] = ex[i] * inv;
        }
    } else {
        float mx = -INFINITY;
        for (int p = beg + lane; p < end; p += 32) {
            int2 de = cde[p];
            float a = sv + s[de.x];
            a = (a >= 0.f) ? a : 0.2f * a;
            mx = fmaxf(mx, a);
        }
#pragma unroll
        for (int o = 16; o > 0; o >>= 1) mx = fmaxf(mx, __shfl_xor_sync(0xffffffffu, mx, o));
        float sum = 0.f;
        for (int p = beg + lane; p < end; p += 32) {
            int2 de = cde[p];
            float a = sv + s[de.x];
            a = (a >= 0.f) ? a : 0.2f * a;
            sum += expf(a - mx);
        }
#pragma unroll
        for (int o = 16; o > 0; o >>= 1) sum += __shfl_xor_sync(0xffffffffu, sum, o);
        float inv = 1.f / (sum + EPS);
        for (int p = beg + lane; p < end; p += 32) {
            int2 de = cde[p];
            float a = sv + s[de.x];
            a = (a >= 0.f) ? a : 0.2f * a;
            alpha[de.y] = expf(a - mx) * inv;
        }
    }
}

// ---------------- aggregation (gather, warp per dst row) ----------------
__global__ __launch_bounds__(256)
void k_agg_gt(const float* __restrict__ H, const int* __restrict__ rp,
              const int* __restrict__ cse, const float* __restrict__ alpha,
              float* __restrict__ out) {
    int node = (blockIdx.x * blockDim.x + threadIdx.x) >> 5;
    if (node >= NN) return;
    int lane = threadIdx.x & 31;
    int beg = rp[node], end = rp[node + 1];
    float ax = 0.f, ay = 0.f, az = 0.f, aw = 0.f;
    if (beg < end) {
        int   sn = __ldg(&cse[beg]);
        float w  = __ldg(&alpha[beg]);
        for (int p = beg; p < end; p++) {
            int   sn_n = 0; float w_n = 0.f;
            if (p + 1 < end) {
                sn_n = __ldg(&cse[p + 1]);
                w_n  = __ldg(&alpha[p + 1]);
            }
            float4 hv = __ldg((const float4*)(H + (size_t)sn * C + lane * 4));
            ax = fmaf(w, hv.x, ax); ay = fmaf(w, hv.y, ay);
            az = fmaf(w, hv.z, az); aw = fmaf(w, hv.w, aw);
            sn = sn_n; w = w_n;
        }
    }
    *(float4*)(out + (size_t)node * C + lane * 4) = make_float4(ax, ay, az, aw);
}

__global__ __launch_bounds__(256)
void k_agg_gcn(const float* __restrict__ H, const int* __restrict__ rp,
               const int* __restrict__ cse, const float* __restrict__ dinv,
               float* __restrict__ out) {
    int node = (blockIdx.x * blockDim.x + threadIdx.x) >> 5;
    if (node >= NN) return;
    int lane = threadIdx.x & 31;
    int beg = rp[node], end = rp[node + 1];
    float dd = dinv[node];
    float ax = 0.f, ay = 0.f, az = 0.f, aw = 0.f;
    if (beg < end) {
        int   sn = __ldg(&cse[beg]);
        float w  = dd * __ldg(&dinv[sn]);
        for (int p = beg; p < end; p++) {
            int sn_n = 0; float w_n = 0.f;
            if (p + 1 < end) {
                sn_n = __ldg(&cse[p + 1]);
                w_n  = dd * __ldg(&dinv[sn_n]);
            }
            float4 hv = __ldg((const float4*)(H + (size_t)sn * C + lane * 4));
            ax = fmaf(w, hv.x, ax); ay = fmaf(w, hv.y, ay);
            az = fmaf(w, hv.z, az); aw = fmaf(w, hv.w, aw);
            sn = sn_n; w = w_n;
        }
    }
    *(float4*)(out + (size_t)node * C + lane * 4) = make_float4(ax, ay, az, aw);
}

// ---------------- pooling (with fused count) + head ----------------
__global__ __launch_bounds__(128)
void k_pool(const float* __restrict__ X, const int* __restrict__ batch,
            float* __restrict__ pool, float* __restrict__ cnt) {
    int c = threadIdx.x;
    int per = (NN + gridDim.x - 1) / gridDim.x;
    int n0 = blockIdx.x * per;
    int n1 = n0 + per; if (n1 > NN) n1 = NN;
    if (n0 >= n1) return;
    float acc = 0.f;
    int cc = 0;
    int curg = batch[n0];
    for (int i = n0; i < n1; i++) {
        int g = batch[i];
        if (g != curg) {
            atomicAdd(&pool[(size_t)curg * C + c], acc);
            if (c == 0) atomicAdd(&cnt[curg], (float)cc);
            acc = 0.f; cc = 0; curg = g;
        }
        acc += X[(size_t)i * C + c];
        cc++;
    }
    atomicAdd(&pool[(size_t)curg * C + c], acc);
    if (c == 0) atomicAdd(&cnt[curg], (float)cc);
}

__global__ void k_head(const float* __restrict__ pool, const float* __restrict__ cnt,
                       const float* __restrict__ bg, const float* __restrict__ Wfc,
                       const float* __restrict__ bfc, float* __restrict__ out) {
    int g = blockIdx.x;
    int lane = threadIdx.x;
    float cg = fmaxf(cnt[g], 1.f);
    float logit = -INFINITY;
    if (lane < OC) {
        float acc = 0.f;
        for (int c = 0; c < C; c++) {
            float p = pool[(size_t)g * C + c] / cg + bg[c];
            acc = fmaf(p, Wfc[c * OC + lane], acc);
        }
        logit = acc + bfc[lane];
    }
    float mx = logit;
#pragma unroll
    for (int o = 16; o > 0; o >>= 1) mx = fmaxf(mx, __shfl_xor_sync(0xffffffffu, mx, o));
    float ex = (lane < OC) ? expf(logit - mx) : 0.f;
    float sm = ex;
#pragma unroll
    for (int o = 16; o > 0; o >>= 1) sm += __shfl_xor_sync(0xffffffffu, sm, o);
    if (lane < OC) out[g * OC + lane] = logit - mx - logf(sm);
}

// ---------------- host orchestration ----------------
extern "C" void kernel_launch(void* const* d_in, const int* in_sizes, int n_in,
                              void* d_out, int out_size) {
    const float* x    = (const float*)d_in[0];
    const int*   ei   = (const int*)  d_in[1];
    const int*   batch= (const int*)  d_in[2];
    const float* W1   = (const float*)d_in[3];
    const float* b1   = (const float*)d_in[4];
    const float* att1 = (const float*)d_in[5];
    const float* W2   = (const float*)d_in[6];
    const float* b2   = (const float*)d_in[7];
    const float* att2 = (const float*)d_in[8];
    const float* Wg   = (const float*)d_in[9];
    const float* bg   = (const float*)d_in[10];
    const float* Wfc  = (const float*)d_in[11];
    const float* bfc  = (const float*)d_in[12];
    float* out = (float*)d_out;

    void *ph, *pt1, *pt2, *ps, *pal, *pdi, *phist, *phist2, *prp, *prp2,
         *pcur, *pcur2, *pcse, *pcde, *pbs, *pbs2, *ppool, *pcnt, *pwf;
    cudaGetSymbolAddress(&ph,    g_h);
    cudaGetSymbolAddress(&pt1,   g_t1);
    cudaGetSymbolAddress(&pt2,   g_t2);
    cudaGetSymbolAddress(&ps,    g_s);
    cudaGetSymbolAddress(&pal,   g_alpha);
    cudaGetSymbolAddress(&pdi,   g_dinv);
    cudaGetSymbolAddress(&phist, g_hist);
    cudaGetSymbolAddress(&phist2,g_hist2);
    cudaGetSymbolAddress(&prp,   g_rp);
    cudaGetSymbolAddress(&prp2,  g_rp2);
    cudaGetSymbolAddress(&pcur,  g_cur);
    cudaGetSymbolAddress(&pcur2, g_cur2);
    cudaGetSymbolAddress(&pcse,  g_cse);
    cudaGetSymbolAddress(&pcde,  g_cde);
    cudaGetSymbolAddress(&pbs,   g_bsum);
    cudaGetSymbolAddress(&pbs2,  g_bsum2);
    cudaGetSymbolAddress(&ppool, g_pool);
    cudaGetSymbolAddress(&pcnt,  g_cnt);
    cudaGetSymbolAddress(&pwf,   g_wfrag);

    float* h     = (float*)ph;    float* t1   = (float*)pt1;
    float* t2    = (float*)pt2;   float* s    = (float*)ps;
    float* alpha = (float*)pal;   float* dinv = (float*)pdi;
    int* hist    = (int*)phist;   int* hist2  = (int*)phist2;
    int* rp      = (int*)prp;     int* rp2    = (int*)prp2;
    int* cur     = (int*)pcur;    int* cur2   = (int*)pcur2;
    int* cse     = (int*)pcse;    int2* cde   = (int2*)pcde;
    int* bsum    = (int*)pbs;     int* bsum2  = (int*)pbs2;
    float* pool  = (float*)ppool; float* cnt  = (float*)pcnt;
    float* wfrag = (float*)pwf;

    cudaFuncSetAttribute(k_gemm_tc, cudaFuncAttributeMaxDynamicSharedMemorySize,
                         GEMM_SMEM_BYTES);

    const int NBN = (NN + 255) / 256;   // 157
    const int NBE = (ET + 255) / 256;   // 2657
    const int NBW = NN / 8;             // 5000 warp-per-node blocks
    const int NBG = NN / 64;            // 625 GEMM blocks

    // ---- init + CSR build (both directions) + weight prep ----
    k_zero_all<<<NBN, 256>>>(hist, hist2, pool, cnt);
    k_wprep<<<96, 256>>>(W1, W2, Wg, wfrag);
    k_hist<<<NBE, 256>>>(ei, hist, hist2);
    k_scan1f<<<80, 1024>>>(hist, hist2, rp, rp2, bsum, bsum2);
    k_scan2f<<<1, 128>>>(bsum, bsum2);
    k_scan3f<<<80, 1024>>>(rp, rp2, bsum, bsum2, cur, cur2);
    k_fill<<<NBE, 256>>>(ei, cur, cur2, cse, cde);
    k_dinv<<<NBN, 256>>>(rp, dinv);

    // ---- GT layer 1 (rowdot fused into GEMM) ----
    k_gemm_tc<<<NBG, 256, GEMM_SMEM_BYTES>>>(x, wfrag, b1, att1, h, s, 0, 1);
    k_softmax<<<NBW, 256>>>(rp2, cde, s, alpha);
    k_agg_gt<<<NBW, 256>>>(h, rp, cse, alpha, t1);

    // ---- GT layer 2 (input relu'd inside gemm) ----
    k_gemm_tc<<<NBG, 256, GEMM_SMEM_BYTES>>>(t1, wfrag + 32768, b2, att2, h, s, 1, 1);
    k_softmax<<<NBW, 256>>>(rp2, cde, s, alpha);
    k_agg_gt<<<NBW, 256>>>(h, rp, cse, alpha, t2);

    // ---- GCN layer (no bias, no rowdot) ----
    k_gemm_tc<<<NBG, 256, GEMM_SMEM_BYTES>>>(t2, wfrag + 65536, (const float*)0,
                                             (const float*)0, h, s, 1, 0);
    k_agg_gcn<<<NBW, 256>>>(h, rp, cse, dinv, t1);

    // ---- pooling + head (bg folded into pooled mean) ----
    k_pool<<<320, 128>>>(t1, batch, pool, cnt);
    k_head<<<NG, 32>>>(pool, cnt, bg, Wfc, bfc, out);
}

// round 6
// speedup vs baseline: 1.4042x; 1.0479x over previous
#include <cuda_runtime.h>
#include <cuda_fp16.h>
#include <math.h>

#define NN 40000
#define NE 640000
#define ET 680000       // NE + NN self loops
#define C  128
#define NG 64
#define OC 16
#define EPS 1e-16f

// ---------------- scratch (device globals; no allocation allowed) ----------------
__device__ __half2  g_hh [(size_t)NN * 64];   // H in fp16 (64 half2 per row)
__device__ float    g_t1 [(size_t)NN * C];
__device__ float    g_t2 [(size_t)NN * C];
__device__ float    g_s  [NN];
__device__ float    g_alpha[ET];
__device__ float    g_dinv[NN];
__device__ int      g_hist [NN];
__device__ int      g_hist2[NN];
__device__ int      g_rp  [NN + 1];
__device__ int      g_rp2 [NN + 1];
__device__ int      g_cur [NN];
__device__ int      g_cur2[NN];
__device__ int      g_cse [ET];   // dst-CSR: src node per slot
__device__ int2     g_cde [ET];   // src-CSR: {dst node, dst-CSR slot}
__device__ int      g_bsum [64];
__device__ int      g_bsum2[64];
__device__ float    g_pool[NG * C];
__device__ float    g_cnt [NG];
__device__ float    g_wfrag[3 * 2 * 16384];  // [mat][hi/lo][16384] frag-ordered tf32

// ---------------- tf32 helpers ----------------
__device__ __forceinline__ unsigned f2tf(float x) {
    unsigned r;
    asm("cvt.rna.tf32.f32 %0, %1;" : "=r"(r) : "f"(x));
    return r;
}

__device__ __forceinline__ void mma_tf32(float c[4], const unsigned a[4],
                                         unsigned b0, unsigned b1) {
    asm volatile(
        "mma.sync.aligned.m16n8k8.row.col.f32.tf32.tf32.f32 "
        "{%0,%1,%2,%3}, {%4,%5,%6,%7}, {%8,%9}, {%0,%1,%2,%3};\n"
        : "+f"(c[0]), "+f"(c[1]), "+f"(c[2]), "+f"(c[3])
        : "r"(a[0]), "r"(a[1]), "r"(a[2]), "r"(a[3]), "r"(b0), "r"(b1));
}

// ---------------- init: weight prep (blocks 0..95) + zero (blocks 96..252) ----------
// frag f = (kk*16 + t)*32 + lane; b0 = W[kk*8+tig][t*8+grp], b1 = W[kk*8+tig+4][t*8+grp]
__global__ void k_init(const float* __restrict__ W1, const float* __restrict__ W2,
                       const float* __restrict__ Wg, float* __restrict__ wfrag,
                       int* __restrict__ hist, int* __restrict__ hist2,
                       float* __restrict__ pool, float* __restrict__ cnt) {
    if (blockIdx.x < 96) {
        int idx = blockIdx.x * 256 + threadIdx.x;
        if (idx >= 3 * 8192) return;
        int mat = idx >> 13;
        int f   = idx & 8191;
        const float* W = (mat == 0) ? W1 : ((mat == 1) ? W2 : Wg);
        int lane = f & 31, t = (f >> 5) & 15, kk = f >> 9;
        int tig = lane & 3, grp = lane >> 2;
        int colN = t * 8 + grp;
        float x0 = W[(kk * 8 + tig) * C + colN];
        float x1 = W[(kk * 8 + tig + 4) * C + colN];
        float* whi = wfrag + (size_t)mat * 32768;
        float* wlo = whi + 16384;
        unsigned h0 = f2tf(x0); float l0 = x0 - __uint_as_float(h0);
        unsigned h1 = f2tf(x1); float l1 = x1 - __uint_as_float(h1);
        whi[f * 2]     = __uint_as_float(h0);
        whi[f * 2 + 1] = __uint_as_float(h1);
        wlo[f * 2]     = __uint_as_float(f2tf(l0));
        wlo[f * 2 + 1] = __uint_as_float(f2tf(l1));
    } else {
        int i = (blockIdx.x - 96) * 256 + threadIdx.x;
        if (i < NN) { hist[i] = 0; hist2[i] = 0; }
        if (i < NG * C) pool[i] = 0.f;
        if (i < NG) cnt[i] = 0.f;
    }
}

// ---------------- CSR build (both directions) ----------------
__global__ void k_hist(const int* __restrict__ ei, int* __restrict__ hist,
                       int* __restrict__ hist2) {
    int e = blockIdx.x * blockDim.x + threadIdx.x;
    if (e >= ET) return;
    int s, d;
    if (e < NE) { s = ei[e]; d = ei[NE + e]; }
    else        { s = d = e - NE; }
    atomicAdd(&hist[d], 1);
    atomicAdd(&hist2[s], 1);
}

// dual-direction block scan (blocks 0..39 -> dir0 (+dinv), 40..79 -> dir1)
__global__ __launch_bounds__(1024)
void k_scan1f(const int* __restrict__ hist, const int* __restrict__ hist2,
              int* __restrict__ rp, int* __restrict__ rp2,
              int* __restrict__ bsum, int* __restrict__ bsum2,
              float* __restrict__ dinv) {
    __shared__ int wsum[32];
    int dir = (blockIdx.x >= 40);
    int blk = blockIdx.x - dir * 40;
    const int* in = dir ? hist2 : hist;
    int* rpo = dir ? rp2 : rp;
    int* bso = dir ? bsum2 : bsum;

    int i = blk * 1024 + threadIdx.x;
    int v = (i < NN) ? in[i] : 0;
    if (!dir && i < NN) dinv[i] = rsqrtf((float)v);   // deg includes self loop -> >=1
    int lane = threadIdx.x & 31, w = threadIdx.x >> 5;
    int inc = v;
#pragma unroll
    for (int off = 1; off < 32; off <<= 1) {
        int t = __shfl_up_sync(0xffffffffu, inc, off);
        if (lane >= off) inc += t;
    }
    if (lane == 31) wsum[w] = inc;
    __syncthreads();
    if (w == 0) {
        int x = wsum[lane];
#pragma unroll
        for (int off = 1; off < 32; off <<= 1) {
            int t = __shfl_up_sync(0xffffffffu, x, off);
            if (lane >= off) x += t;
        }
        wsum[lane] = x;
    }
    __syncthreads();
    int wpre = (w > 0) ? wsum[w - 1] : 0;
    if (i < NN) rpo[i] = wpre + inc - v;
    if (threadIdx.x == 1023) bso[blk] = wpre + inc;
}

__global__ void k_scan2f(int* __restrict__ bsum, int* __restrict__ bsum2) {
    __shared__ int sm[128];
    int tid = threadIdx.x;
    int half = tid >> 6, idx = tid & 63;
    int* bs = half ? bsum2 : bsum;
    int v = (idx < 40) ? bs[idx] : 0;
    sm[tid] = v;
    __syncthreads();
    for (int off = 1; off < 64; off <<= 1) {
        int t = (idx >= off) ? sm[tid - off] : 0;
        __syncthreads();
        sm[tid] += t;
        __syncthreads();
    }
    if (idx < 40) bs[idx] = sm[tid] - v;
}

__global__ __launch_bounds__(1024)
void k_scan3f(int* __restrict__ rp, int* __restrict__ rp2,
              const int* __restrict__ bsum, const int* __restrict__ bsum2,
              int* __restrict__ cur, int* __restrict__ cur2) {
    int dir = (blockIdx.x >= 40);
    int blk = blockIdx.x - dir * 40;
    int* rpo  = dir ? rp2  : rp;
    int* curo = dir ? cur2 : cur;
    const int* bso = dir ? bsum2 : bsum;
    int i = blk * 1024 + threadIdx.x;
    if (i < NN) {
        int r = rpo[i] + bso[blk];
        rpo[i]  = r;
        curo[i] = r;
    }
    if (blk == 0 && threadIdx.x == 0) rpo[NN] = ET;
}

__global__ void k_fill(const int* __restrict__ ei, int* __restrict__ cur,
                       int* __restrict__ cur2, int* __restrict__ cse,
                       int2* __restrict__ cde) {
    int e = blockIdx.x * blockDim.x + threadIdx.x;
    if (e >= ET) return;
    int s, d;
    if (e < NE) { s = ei[e]; d = ei[NE + e]; }
    else        { s = d = e - NE; }
    int pos = atomicAdd(&cur[d], 1);
    cse[pos] = s;
    int pos2 = atomicAdd(&cur2[s], 1);
    cde[pos2] = make_int2(d, pos);
}

// ---------------- GEMM + fused rowdot; fp16 H output ----------------
// BM=64, BN=128, K=128. 8 warps: 2(m) x 4(n), warp tile 32x32.
#define GEMM_SMEM_FLOATS (64 * 132 * 2 + 32768)
#define GEMM_SMEM_BYTES  (GEMM_SMEM_FLOATS * 4)

__global__ __launch_bounds__(256)
void k_gemm_tc(const float* __restrict__ X, const float* __restrict__ wfrag,
               const float* __restrict__ Bb, const float* __restrict__ att,
               __half2* __restrict__ Hh, float* __restrict__ sOut,
               int relu_in, int has_bias) {
    extern __shared__ float smf[];
    float* Xh = smf;                     // [64][132] tf32-hi
    float* Xl = smf + 64 * 132;          // [64][132] tf32-lo
    float* Wh = smf + 2 * 64 * 132;      // [16384] frag-ordered
    float* Wl = Wh + 16384;

    int tid  = threadIdx.x;
    int row0 = blockIdx.x * 64;

    // stage X tile, split hi/lo
    const float4* xg = (const float4*)(X + (size_t)row0 * C);
#pragma unroll
    for (int i = 0; i < 8; i++) {
        int idx = tid + i * 256;              // 2048 float4 = 64 rows x 32
        float4 v = xg[idx];
        if (relu_in) {
            v.x = fmaxf(v.x, 0.f); v.y = fmaxf(v.y, 0.f);
            v.z = fmaxf(v.z, 0.f); v.w = fmaxf(v.w, 0.f);
        }
        int r  = idx >> 5;
        int c0 = (idx & 31) * 4;
        float xv[4] = {v.x, v.y, v.z, v.w};
#pragma unroll
        for (int j = 0; j < 4; j++) {
            unsigned hi = f2tf(xv[j]);
            float lo = xv[j] - __uint_as_float(hi);
            Xh[r * 132 + c0 + j] = __uint_as_float(hi);
            Xl[r * 132 + c0 + j] = __uint_as_float(f2tf(lo));
        }
    }
    // stage W frags
    {
        const float4* wg = (const float4*)wfrag;
        float4* ws = (float4*)Wh;
#pragma unroll
        for (int i = tid; i < 8192; i += 256) ws[i] = wg[i];
    }
    __syncthreads();

    int wid = tid >> 5, lane = tid & 31;
    int mw = wid & 1, nw = wid >> 1;
    int m0  = mw * 32;
    int n0g = nw * 4;
    int grp = lane >> 2, tig = lane & 3;

    float acc[2][4][4];
#pragma unroll
    for (int ms = 0; ms < 2; ms++)
#pragma unroll
        for (int t = 0; t < 4; t++)
#pragma unroll
            for (int j = 0; j < 4; j++) acc[ms][t][j] = 0.f;

#pragma unroll
    for (int kk = 0; kk < 16; kk++) {
        unsigned ah[2][4], al[2][4];
#pragma unroll
        for (int ms = 0; ms < 2; ms++) {
            int ar = m0 + ms * 16 + grp;
            int ac = kk * 8 + tig;
            ah[ms][0] = __float_as_uint(Xh[ar * 132 + ac]);
            ah[ms][1] = __float_as_uint(Xh[(ar + 8) * 132 + ac]);
            ah[ms][2] = __float_as_uint(Xh[ar * 132 + ac + 4]);
            ah[ms][3] = __float_as_uint(Xh[(ar + 8) * 132 + ac + 4]);
            al[ms][0] = __float_as_uint(Xl[ar * 132 + ac]);
            al[ms][1] = __float_as_uint(Xl[(ar + 8) * 132 + ac]);
            al[ms][2] = __float_as_uint(Xl[ar * 132 + ac + 4]);
            al[ms][3] = __float_as_uint(Xl[(ar + 8) * 132 + ac + 4]);
        }
#pragma unroll
        for (int t = 0; t < 4; t++) {
            int f = (kk * 16 + n0g + t) * 32 + lane;
            uint2 bh = *(const uint2*)(Wh + f * 2);
            uint2 bl = *(const uint2*)(Wl + f * 2);
#pragma unroll
            for (int ms = 0; ms < 2; ms++) {
                mma_tf32(acc[ms][t], ah[ms], bh.x, bh.y);   // hi*hi
                mma_tf32(acc[ms][t], al[ms], bh.x, bh.y);   // lo*hi
                mma_tf32(acc[ms][t], ah[ms], bl.x, bl.y);   // hi*lo
            }
        }
    }

    // epilogue: bias add, fp16 H store, fused att rowdot (fp32-exact)
    float part[4] = {0.f, 0.f, 0.f, 0.f};
    bool do_dot = (att != 0);
#pragma unroll
    for (int t = 0; t < 4; t++) {
        int col = (n0g + t) * 8 + tig * 2;      // even column
        float2 bv = make_float2(0.f, 0.f);
        if (has_bias) bv = *(const float2*)(Bb + col);
        float2 av = make_float2(0.f, 0.f);
        if (do_dot) av = __ldg((const float2*)(att + col));
#pragma unroll
        for (int ms = 0; ms < 2; ms++) {
            int row = row0 + m0 + ms * 16 + grp;
            float o0 = acc[ms][t][0] + bv.x, o1 = acc[ms][t][1] + bv.y;
            float o2 = acc[ms][t][2] + bv.x, o3 = acc[ms][t][3] + bv.y;
            Hh[(size_t)row * 64 + (col >> 1)]       = __floats2half2_rn(o0, o1);
            Hh[(size_t)(row + 8) * 64 + (col >> 1)] = __floats2half2_rn(o2, o3);
            part[ms * 2]     += o0 * av.x + o1 * av.y;
            part[ms * 2 + 1] += o2 * av.x + o3 * av.y;
        }
    }
    if (do_dot) {
        __syncthreads();
        float* sarr = smf;
        if (tid < 64) sarr[tid] = 0.f;
        __syncthreads();
        atomicAdd(&sarr[m0 + grp],      part[0]);
        atomicAdd(&sarr[m0 + grp + 8],  part[1]);
        atomicAdd(&sarr[m0 + grp + 16], part[2]);
        atomicAdd(&sarr[m0 + grp + 24], part[3]);
        __syncthreads();
        if (tid < 64) sOut[row0 + tid] = sarr[tid];
    }
}

// ---------------- fused softmax over src groups (warp per src node) ----------------
__global__ __launch_bounds__(256)
void k_softmax(const int* __restrict__ rp2, const int2* __restrict__ cde,
               const float* __restrict__ s, float* __restrict__ alpha) {
    int node = (blockIdx.x * blockDim.x + threadIdx.x) >> 5;
    if (node >= NN) return;
    int lane = threadIdx.x & 31;
    int beg = rp2[node], end = rp2[node + 1];
    int deg = end - beg;
    float sv = s[node];

    if (deg <= 128) {
        float ex[4];
        int   slot[4];
        int k = 0;
        float mx = -INFINITY;
        for (int p = beg + lane; p < end; p += 32, k++) {
            int2 de = __ldg(&cde[p]);
            float a = sv + __ldg(&s[de.x]);
            a = (a >= 0.f) ? a : 0.2f * a;
            ex[k] = a; slot[k] = de.y;
            mx = fmaxf(mx, a);
        }
#pragma unroll
        for (int o = 16; o > 0; o >>= 1) mx = fmaxf(mx, __shfl_xor_sync(0xffffffffu, mx, o));
        float sum = 0.f;
#pragma unroll
        for (int i = 0; i < 4; i++) {
            if (i < k) { ex[i] = expf(ex[i] - mx); sum += ex[i]; }
        }
#pragma unroll
        for (int o = 16; o > 0; o >>= 1) sum += __shfl_xor_sync(0xffffffffu, sum, o);
        float inv = 1.f / (sum + EPS);
#pragma unroll
        for (int i = 0; i < 4; i++) {
            if (i < k) alpha[slot[i]] = ex[i] * inv;
        }
    } else {
        float mx = -INFINITY;
        for (int p = beg + lane; p < end; p += 32) {
            int2 de = cde[p];
            float a = sv + s[de.x];
            a = (a >= 0.f) ? a : 0.2f * a;
            mx = fmaxf(mx, a);
        }
#pragma unroll
        for (int o = 16; o > 0; o >>= 1) mx = fmaxf(mx, __shfl_xor_sync(0xffffffffu, mx, o));
        float sum = 0.f;
        for (int p = beg + lane; p < end; p += 32) {
            int2 de = cde[p];
            float a = sv + s[de.x];
            a = (a >= 0.f) ? a : 0.2f * a;
            sum += expf(a - mx);
        }
#pragma unroll
        for (int o = 16; o > 0; o >>= 1) sum += __shfl_xor_sync(0xffffffffu, sum, o);
        float inv = 1.f / (sum + EPS);
        for (int p = beg + lane; p < end; p += 32) {
            int2 de = cde[p];
            float a = sv + s[de.x];
            a = (a >= 0.f) ? a : 0.2f * a;
            alpha[de.y] = expf(a - mx) * inv;
        }
    }
}

// ---------------- aggregation (fp16 gather, warp per dst row) ----------------
__global__ __launch_bounds__(256)
void k_agg_gt(const __half2* __restrict__ Hh, const int* __restrict__ rp,
              const int* __restrict__ cse, const float* __restrict__ alpha,
              float* __restrict__ out) {
    int node = (blockIdx.x * blockDim.x + threadIdx.x) >> 5;
    if (node >= NN) return;
    int lane = threadIdx.x & 31;
    int beg = rp[node], end = rp[node + 1];
    float ax = 0.f, ay = 0.f, az = 0.f, aw = 0.f;
    if (beg < end) {
        int   sn = __ldg(&cse[beg]);
        float w  = __ldg(&alpha[beg]);
        for (int p = beg; p < end; p++) {
            int sn_n = 0; float w_n = 0.f;
            if (p + 1 < end) {
                sn_n = __ldg(&cse[p + 1]);
                w_n  = __ldg(&alpha[p + 1]);
            }
            uint2 u = __ldg((const uint2*)(Hh + (size_t)sn * 64) + lane);
            float2 f0 = __half22float2(*(const __half2*)&u.x);
            float2 f1 = __half22float2(*(const __half2*)&u.y);
            ax = fmaf(w, f0.x, ax); ay = fmaf(w, f0.y, ay);
            az = fmaf(w, f1.x, az); aw = fmaf(w, f1.y, aw);
            sn = sn_n; w = w_n;
        }
    }
    *(float4*)(out + (size_t)node * C + lane * 4) = make_float4(ax, ay, az, aw);
}

__global__ __launch_bounds__(256)
void k_agg_gcn(const __half2* __restrict__ Hh, const int* __restrict__ rp,
               const int* __restrict__ cse, const float* __restrict__ dinv,
               float* __restrict__ out) {
    int node = (blockIdx.x * blockDim.x + threadIdx.x) >> 5;
    if (node >= NN) return;
    int lane = threadIdx.x & 31;
    int beg = rp[node], end = rp[node + 1];
    float dd = dinv[node];
    float ax = 0.f, ay = 0.f, az = 0.f, aw = 0.f;
    if (beg < end) {
        int   sn = __ldg(&cse[beg]);
        float w  = dd * __ldg(&dinv[sn]);
        for (int p = beg; p < end; p++) {
            int sn_n = 0; float w_n = 0.f;
            if (p + 1 < end) {
                sn_n = __ldg(&cse[p + 1]);
                w_n  = dd * __ldg(&dinv[sn_n]);
            }
            uint2 u = __ldg((const uint2*)(Hh + (size_t)sn * 64) + lane);
            float2 f0 = __half22float2(*(const __half2*)&u.x);
            float2 f1 = __half22float2(*(const __half2*)&u.y);
            ax = fmaf(w, f0.x, ax); ay = fmaf(w, f0.y, ay);
            az = fmaf(w, f1.x, az); aw = fmaf(w, f1.y, aw);
            sn = sn_n; w = w_n;
        }
    }
    *(float4*)(out + (size_t)node * C + lane * 4) = make_float4(ax, ay, az, aw);
}

// ---------------- pooling (with fused count) + head ----------------
__global__ __launch_bounds__(128)
void k_pool(const float* __restrict__ X, const int* __restrict__ batch,
            float* __restrict__ pool, float* __restrict__ cnt) {
    int c = threadIdx.x;
    int per = (NN + gridDim.x - 1) / gridDim.x;
    int n0 = blockIdx.x * per;
    int n1 = n0 + per; if (n1 > NN) n1 = NN;
    if (n0 >= n1) return;
    float acc = 0.f;
    int cc = 0;
    int curg = batch[n0];
    for (int i = n0; i < n1; i++) {
        int g = batch[i];
        if (g != curg) {
            atomicAdd(&pool[(size_t)curg * C + c], acc);
            if (c == 0) atomicAdd(&cnt[curg], (float)cc);
            acc = 0.f; cc = 0; curg = g;
        }
        acc += X[(size_t)i * C + c];
        cc++;
    }
    atomicAdd(&pool[(size_t)curg * C + c], acc);
    if (c == 0) atomicAdd(&cnt[curg], (float)cc);
}

__global__ void k_head(const float* __restrict__ pool, const float* __restrict__ cnt,
                       const float* __restrict__ bg, const float* __restrict__ Wfc,
                       const float* __restrict__ bfc, float* __restrict__ out) {
    int g = blockIdx.x;
    int lane = threadIdx.x;
    float cg = fmaxf(cnt[g], 1.f);
    float logit = -INFINITY;
    if (lane < OC) {
        float acc = 0.f;
        for (int c = 0; c < C; c++) {
            float p = pool[(size_t)g * C + c] / cg + bg[c];
            acc = fmaf(p, Wfc[c * OC + lane], acc);
        }
        logit = acc + bfc[lane];
    }
    float mx = logit;
#pragma unroll
    for (int o = 16; o > 0; o >>= 1) mx = fmaxf(mx, __shfl_xor_sync(0xffffffffu, mx, o));
    float ex = (lane < OC) ? expf(logit - mx) : 0.f;
    float sm = ex;
#pragma unroll
    for (int o = 16; o > 0; o >>= 1) sm += __shfl_xor_sync(0xffffffffu, sm, o);
    if (lane < OC) out[g * OC + lane] = logit - mx - logf(sm);
}

// ---------------- host orchestration ----------------
extern "C" void kernel_launch(void* const* d_in, const int* in_sizes, int n_in,
                              void* d_out, int out_size) {
    const float* x    = (const float*)d_in[0];
    const int*   ei   = (const int*)  d_in[1];
    const int*   batch= (const int*)  d_in[2];
    const float* W1   = (const float*)d_in[3];
    const float* b1   = (const float*)d_in[4];
    const float* att1 = (const float*)d_in[5];
    const float* W2   = (const float*)d_in[6];
    const float* b2   = (const float*)d_in[7];
    const float* att2 = (const float*)d_in[8];
    const float* Wg   = (const float*)d_in[9];
    const float* bg   = (const float*)d_in[10];
    const float* Wfc  = (const float*)d_in[11];
    const float* bfc  = (const float*)d_in[12];
    float* out = (float*)d_out;

    void *phh, *pt1, *pt2, *ps, *pal, *pdi, *phist, *phist2, *prp, *prp2,
         *pcur, *pcur2, *pcse, *pcde, *pbs, *pbs2, *ppool, *pcnt, *pwf;
    cudaGetSymbolAddress(&phh,   g_hh);
    cudaGetSymbolAddress(&pt1,   g_t1);
    cudaGetSymbolAddress(&pt2,   g_t2);
    cudaGetSymbolAddress(&ps,    g_s);
    cudaGetSymbolAddress(&pal,   g_alpha);
    cudaGetSymbolAddress(&pdi,   g_dinv);
    cudaGetSymbolAddress(&phist, g_hist);
    cudaGetSymbolAddress(&phist2,g_hist2);
    cudaGetSymbolAddress(&prp,   g_rp);
    cudaGetSymbolAddress(&prp2,  g_rp2);
    cudaGetSymbolAddress(&pcur,  g_cur);
    cudaGetSymbolAddress(&pcur2, g_cur2);
    cudaGetSymbolAddress(&pcse,  g_cse);
    cudaGetSymbolAddress(&pcde,  g_cde);
    cudaGetSymbolAddress(&pbs,   g_bsum);
    cudaGetSymbolAddress(&pbs2,  g_bsum2);
    cudaGetSymbolAddress(&ppool, g_pool);
    cudaGetSymbolAddress(&pcnt,  g_cnt);
    cudaGetSymbolAddress(&pwf,   g_wfrag);

    __half2* hh  = (__half2*)phh;
    float* t1    = (float*)pt1;   float* t2   = (float*)pt2;
    float* s     = (float*)ps;    float* alpha = (float*)pal;
    float* dinv  = (float*)pdi;   int* hist   = (int*)phist;
    int* hist2   = (int*)phist2;  int* rp     = (int*)prp;
    int* rp2     = (int*)prp2;    int* cur    = (int*)pcur;
    int* cur2    = (int*)pcur2;   int* cse    = (int*)pcse;
    int2* cde    = (int2*)pcde;   int* bsum   = (int*)pbs;
    int* bsum2   = (int*)pbs2;    float* pool = (float*)ppool;
    float* cnt   = (float*)pcnt;  float* wfrag = (float*)pwf;

    cudaFuncSetAttribute(k_gemm_tc, cudaFuncAttributeMaxDynamicSharedMemorySize,
                         GEMM_SMEM_BYTES);

    const int NBE = (ET + 255) / 256;   // 2657
    const int NBW = NN / 8;             // 5000 warp-per-node blocks
    const int NBG = NN / 64;            // 625 GEMM blocks

    // ---- init (wprep + zero fused) + CSR build ----
    k_init<<<96 + 157, 256>>>(W1, W2, Wg, wfrag, hist, hist2, pool, cnt);
    k_hist<<<NBE, 256>>>(ei, hist, hist2);
    k_scan1f<<<80, 1024>>>(hist, hist2, rp, rp2, bsum, bsum2, dinv);
    k_scan2f<<<1, 128>>>(bsum, bsum2);
    k_scan3f<<<80, 1024>>>(rp, rp2, bsum, bsum2, cur, cur2);
    k_fill<<<NBE, 256>>>(ei, cur, cur2, cse, cde);

    // ---- GT layer 1 (rowdot fused into GEMM) ----
    k_gemm_tc<<<NBG, 256, GEMM_SMEM_BYTES>>>(x, wfrag, b1, att1, hh, s, 0, 1);
    k_softmax<<<NBW, 256>>>(rp2, cde, s, alpha);
    k_agg_gt<<<NBW, 256>>>(hh, rp, cse, alpha, t1);

    // ---- GT layer 2 (input relu'd inside gemm) ----
    k_gemm_tc<<<NBG, 256, GEMM_SMEM_BYTES>>>(t1, wfrag + 32768, b2, att2, hh, s, 1, 1);
    k_softmax<<<NBW, 256>>>(rp2, cde, s, alpha);
    k_agg_gt<<<NBW, 256>>>(hh, rp, cse, alpha, t2);

    // ---- GCN layer (no bias, no rowdot) ----
    k_gemm_tc<<<NBG, 256, GEMM_SMEM_BYTES>>>(t2, wfrag + 65536, (const float*)0,
                                             (const float*)0, hh, s, 1, 0);
    k_agg_gcn<<<NBW, 256>>>(hh, rp, cse, dinv, t1);

    // ---- pooling + head (bg folded into pooled mean) ----
    k_pool<<<320, 128>>>(t1, batch, pool, cnt);
    k_head<<<NG, 32>>>(pool, cnt, bg, Wfc, bfc, out);
}